// round 2
// baseline (speedup 1.0000x reference)
#include <cuda_runtime.h>
#include <cuda_bf16.h>
#include <math.h>
#include <stdint.h>

// Problem constants (fixed for this instance)
#define B 32
#define T 128
#define E 512
#define H 1024
#define V 32000
#define L 64          // max_len
#define BOS 1

// Logits kernel tiling: 8 warps/CTA, 8 vocab per warp => 64 vocab/CTA
#define LOG_VPW 8
#define LOG_VPB 64
#define LOG_NBLK (V / LOG_VPB)   // 500

// ---------------- static device scratch (no allocations allowed) ----------------
__device__ float g_xsT[T * E * B];          // encoder inputs, transposed [t][k][b]
__device__ float g_xdT[E * B];              // decoder step input, [k][b]
__device__ float g_h0T[2][H * B];           // layer-0 hidden ping-pong, [k][b]
__device__ float g_h1T[2][H * B];           // layer-1 hidden ping-pong
__device__ float g_c0T[H * B];              // cells (in-place per step)
__device__ float g_c1T[H * B];
__device__ int   g_tok[B];
__device__ float g_pval[LOG_NBLK * B];      // argmax partials
__device__ int   g_pidx[LOG_NBLK * B];

// ---------------- helpers ----------------
__device__ __forceinline__ float sigm(float x) { return 1.0f / (1.0f + expf(-x)); }

// ---------------- init: zero states, tok=BOS ----------------
__global__ void init_kernel()
{
    int i = blockIdx.x * blockDim.x + threadIdx.x;
    if (i < H * B) {
        g_h0T[0][i] = 0.f;
        g_h1T[0][i] = 0.f;
        g_c0T[i] = 0.f;
        g_c1T[i] = 0.f;
    }
    if (i < B) g_tok[i] = BOS;
}

// ---------------- gather + transpose embedding rows ----------------
// Produces xT[t][k][b] = emb[ tokens[b*tokStride + t] ][k]
// grid: (E/128, nT), block 256
__global__ __launch_bounds__(256) void gather_x_kernel(
    const float* __restrict__ emb,
    const int*   __restrict__ tokens,
    int tokStride,
    float* __restrict__ xT)
{
    __shared__ float tile[B][132];  // 32 rows x 128 k (+pad)
    const int t  = blockIdx.y;
    const int k0 = blockIdx.x * 128;
    const int w = threadIdx.x >> 5, lane = threadIdx.x & 31;

    // load: warp w handles batches 4w..4w+3, coalesced float4 along k
    #pragma unroll
    for (int r = 0; r < 4; r++) {
        int b = w * 4 + r;
        int tokb = tokens[b * tokStride + t];
        float4 v = *(const float4*)(emb + (size_t)tokb * E + k0 + lane * 4);
        tile[b][lane * 4 + 0] = v.x;
        tile[b][lane * 4 + 1] = v.y;
        tile[b][lane * 4 + 2] = v.z;
        tile[b][lane * 4 + 3] = v.w;
    }
    __syncthreads();

    float* out = xT + (size_t)t * E * B + (size_t)k0 * B;
    #pragma unroll
    for (int i = 0; i < 4; i++) {
        int idx = threadIdx.x + i * 256;     // 0..1023
        int k   = idx >> 3;                   // 0..127
        int b4  = (idx & 7) * 4;
        float4 v = make_float4(tile[b4 + 0][k], tile[b4 + 1][k],
                               tile[b4 + 2][k], tile[b4 + 3][k]);
        *(float4*)(out + k * B + b4) = v;     // coalesced
    }
}

// ---------------- fused LSTM step (gates GEMV + cell update) ----------------
// gates[b][g*H+j] = sum_k x[b][k]*Wih[g*H+j][k] + sum_k h[b][k]*Whh[g*H+j][k] + bias
// x given as xT [KX][B], h as hT [H][B]. Warp = one column j, lane = batch.
// grid 128, block 256 (8 warps -> 8 columns/CTA).
__global__ __launch_bounds__(256) void lstm_step_kernel(
    const float* __restrict__ xT, int KX,
    const float* __restrict__ hT,
    const float* __restrict__ Wih,
    const float* __restrict__ Whh,
    const float* __restrict__ bias,
    float* __restrict__ cT,
    float* __restrict__ hT_out)
{
    __shared__ float sx[128 * B];   // one 128-k chunk of activations
    const int tid = threadIdx.x;
    const int w = tid >> 5, lane = tid & 31;
    const int j = blockIdx.x * 8 + w;   // output column 0..H-1

    float ai = 0.f, af = 0.f, ag = 0.f, ao = 0.f;
    const int KT = KX + H;

    for (int kb = 0; kb < KT; kb += 128) {
        // stage chunk (coalesced float4)
        const float4* src4 = (kb < KX) ? (const float4*)(xT + (size_t)kb * B)
                                       : (const float4*)(hT + (size_t)(kb - KX) * B);
        float4* s4 = (float4*)sx;
        #pragma unroll
        for (int i = 0; i < 4; i++) s4[tid + i * 256] = src4[tid + i * 256];
        __syncthreads();

        const float* base; int rstride, koff;
        if (kb < KX) { base = Wih; rstride = KX; koff = kb; }
        else         { base = Whh; rstride = H;  koff = kb - KX; }
        const float4* W0 = (const float4*)(base + (size_t)(0 * H + j) * rstride + koff);
        const float4* W1 = (const float4*)(base + (size_t)(1 * H + j) * rstride + koff);
        const float4* W2 = (const float4*)(base + (size_t)(2 * H + j) * rstride + koff);
        const float4* W3 = (const float4*)(base + (size_t)(3 * H + j) * rstride + koff);

        #pragma unroll 8
        for (int kk = 0; kk < 32; kk++) {
            float4 vi = W0[kk], vf = W1[kk], vg = W2[kk], vo = W3[kk];
            const float* xs = sx + kk * 128 + lane;
            float x0 = xs[0], x1 = xs[32], x2 = xs[64], x3 = xs[96];
            ai += vi.x * x0; ai += vi.y * x1; ai += vi.z * x2; ai += vi.w * x3;
            af += vf.x * x0; af += vf.y * x1; af += vf.z * x2; af += vf.w * x3;
            ag += vg.x * x0; ag += vg.y * x1; ag += vg.z * x2; ag += vg.w * x3;
            ao += vo.x * x0; ao += vo.y * x1; ao += vo.z * x2; ao += vo.w * x3;
        }
        __syncthreads();
    }

    ai += bias[j]; af += bias[H + j]; ag += bias[2 * H + j]; ao += bias[3 * H + j];

    float c_old = cT[j * B + lane];
    float c_new = sigm(af) * c_old + sigm(ai) * tanhf(ag);
    float h_new = sigm(ao) * tanhf(c_new);
    cT[j * B + lane]     = c_new;
    hT_out[j * B + lane] = h_new;
}

// ---------------- logits GEMV + store + argmax partials ----------------
// logits[b][v] = sum_k h1[b][k]*outW[v][k] + outB[v]
// grid LOG_NBLK, block 256. warp -> 8 vocab, lane = batch.
__global__ __launch_bounds__(256) void logits_kernel(
    const float* __restrict__ h1T,
    const float* __restrict__ outW,
    const float* __restrict__ outB,
    float* __restrict__ out, int s)
{
    __shared__ float sx[128 * B];
    __shared__ float sbv[8][B];
    __shared__ int   sbi[8][B];
    const int tid = threadIdx.x;
    const int w = tid >> 5, lane = tid & 31;
    const int vbase = blockIdx.x * LOG_VPB + w * LOG_VPW;

    float acc[LOG_VPW];
    #pragma unroll
    for (int v = 0; v < LOG_VPW; v++) acc[v] = 0.f;

    const float4* Wr[LOG_VPW];
    #pragma unroll
    for (int v = 0; v < LOG_VPW; v++)
        Wr[v] = (const float4*)(outW + (size_t)(vbase + v) * H);

    for (int kb = 0; kb < H; kb += 128) {
        const float4* src4 = (const float4*)(h1T + (size_t)kb * B);
        float4* s4 = (float4*)sx;
        #pragma unroll
        for (int i = 0; i < 4; i++) s4[tid + i * 256] = src4[tid + i * 256];
        __syncthreads();

        const int kq = kb >> 2;
        #pragma unroll 4
        for (int kk = 0; kk < 32; kk++) {
            const float* xs = sx + kk * 128 + lane;
            float x0 = xs[0], x1 = xs[32], x2 = xs[64], x3 = xs[96];
            #pragma unroll
            for (int v = 0; v < LOG_VPW; v++) {
                float4 wv = Wr[v][kq + kk];
                acc[v] += wv.x * x0; acc[v] += wv.y * x1;
                acc[v] += wv.z * x2; acc[v] += wv.w * x3;
            }
        }
        __syncthreads();
    }

    // bias + store + per-lane argmax over this warp's 8 vocab (ascending v => first-max)
    float bv = -INFINITY; int bi = 0;
    float* orow = out + (size_t)lane * L * V + (size_t)s * V;
    #pragma unroll
    for (int v = 0; v < LOG_VPW; v++) {
        float val = acc[v] + outB[vbase + v];
        orow[vbase + v] = val;
        if (val > bv) { bv = val; bi = vbase + v; }
    }
    sbv[w][lane] = bv; sbi[w][lane] = bi;
    __syncthreads();
    if (w == 0) {
        float BV = sbv[0][lane]; int BI = sbi[0][lane];
        #pragma unroll
        for (int q = 1; q < 8; q++) {
            float v2 = sbv[q][lane]; int i2 = sbi[q][lane];
            if (v2 > BV || (v2 == BV && i2 < BI)) { BV = v2; BI = i2; }
        }
        g_pval[blockIdx.x * B + lane] = BV;
        g_pidx[blockIdx.x * B + lane] = BI;
    }
}

// ---------------- argmax final reduce (first-index tie-break) ----------------
__global__ __launch_bounds__(1024) void argmax_final_kernel()
{
    const int w = threadIdx.x >> 5;   // warp = batch (32 warps)
    const int lane = threadIdx.x & 31;
    float bv = -INFINITY; int bi = 0x7fffffff;
    for (int c = lane; c < LOG_NBLK; c += 32) {
        float v = g_pval[c * B + w]; int i = g_pidx[c * B + w];
        if (v > bv || (v == bv && i < bi)) { bv = v; bi = i; }
    }
    #pragma unroll
    for (int off = 16; off; off >>= 1) {
        float v = __shfl_down_sync(0xffffffffu, bv, off);
        int   i = __shfl_down_sync(0xffffffffu, bi, off);
        if (v > bv || (v == bv && i < bi)) { bv = v; bi = i; }
    }
    if (lane == 0) g_tok[w] = bi;
}

// ---------------- host orchestration ----------------
extern "C" void kernel_launch(void* const* d_in, const int* in_sizes, int n_in,
                              void* d_out, int out_size)
{
    const int*   src      = (const int*)  d_in[0];
    const float* emb      = (const float*)d_in[1];
    const float* eWih0    = (const float*)d_in[2];
    const float* eWhh0    = (const float*)d_in[3];
    const float* eb0      = (const float*)d_in[4];
    const float* eWih1    = (const float*)d_in[5];
    const float* eWhh1    = (const float*)d_in[6];
    const float* eb1      = (const float*)d_in[7];
    const float* dWih0    = (const float*)d_in[8];
    const float* dWhh0    = (const float*)d_in[9];
    const float* db0      = (const float*)d_in[10];
    const float* dWih1    = (const float*)d_in[11];
    const float* dWhh1    = (const float*)d_in[12];
    const float* db1      = (const float*)d_in[13];
    const float* outW     = (const float*)d_in[14];
    const float* outB     = (const float*)d_in[15];
    float* out = (float*)d_out;

    float *xsT, *xdT, *h0T, *h1T, *c0T, *c1T;
    int *tok;
    cudaGetSymbolAddress((void**)&xsT, g_xsT);
    cudaGetSymbolAddress((void**)&xdT, g_xdT);
    cudaGetSymbolAddress((void**)&h0T, g_h0T);
    cudaGetSymbolAddress((void**)&h1T, g_h1T);
    cudaGetSymbolAddress((void**)&c0T, g_c0T);
    cudaGetSymbolAddress((void**)&c1T, g_c1T);
    cudaGetSymbolAddress((void**)&tok, g_tok);

    // zero states + BOS token
    init_kernel<<<(H * B + 255) / 256, 256>>>();

    // encoder input gather+transpose for all timesteps
    gather_x_kernel<<<dim3(E / 128, T), 256>>>(emb, src, T, xsT);

    int p0 = 0, p1 = 0;
    // ---- encoder ----
    for (int t = 0; t < T; t++) {
        lstm_step_kernel<<<128, 256>>>(xsT + (size_t)t * E * B, E,
                                       h0T + p0 * H * B,
                                       eWih0, eWhh0, eb0,
                                       c0T, h0T + (1 - p0) * H * B);
        p0 ^= 1;
        lstm_step_kernel<<<128, 256>>>(h0T + p0 * H * B, H,
                                       h1T + p1 * H * B,
                                       eWih1, eWhh1, eb1,
                                       c1T, h1T + (1 - p1) * H * B);
        p1 ^= 1;
    }

    // ---- greedy decoder ----
    for (int s = 0; s < L; s++) {
        gather_x_kernel<<<dim3(E / 128, 1), 256>>>(emb, tok, 1, xdT);
        lstm_step_kernel<<<128, 256>>>(xdT, E,
                                       h0T + p0 * H * B,
                                       dWih0, dWhh0, db0,
                                       c0T, h0T + (1 - p0) * H * B);
        p0 ^= 1;
        lstm_step_kernel<<<128, 256>>>(h0T + p0 * H * B, H,
                                       h1T + p1 * H * B,
                                       dWih1, dWhh1, db1,
                                       c1T, h1T + (1 - p1) * H * B);
        p1 ^= 1;
        logits_kernel<<<LOG_NBLK, 256>>>(h1T + p1 * H * B, outW, outB, out, s);
        argmax_final_kernel<<<1, 1024>>>();
    }
}

// round 5
// speedup vs baseline: 1.6299x; 1.6299x over previous
#include <cuda_runtime.h>
#include <cuda_bf16.h>
#include <math.h>
#include <stdint.h>

// Problem constants
#define B 32
#define T 128
#define E 512
#define H 1024
#define V 32000
#define L 64
#define BOS 1

#define NB 512            // persistent grid size (CTAs)
#define LOG_CTAS 500      // CTAs doing logits work (64 vocab rows each)

// ---------------- static device scratch ----------------
__device__ float g_xsT[T * E * B];      // encoder inputs [t][k][b]
__device__ float g_xdT[E * B];          // decoder step input [k][b]
__device__ float g_h0T[2][H * B];
__device__ float g_h1T[2][H * B];
__device__ float g_c0T[H * B];
__device__ float g_c1T[H * B];
__device__ int   g_tok[B];
__device__ float g_pval[LOG_CTAS * B];
__device__ int   g_pidx[LOG_CTAS * B];
__device__ unsigned g_bar_count;
__device__ unsigned g_bar_gen;

__device__ __forceinline__ float sigm(float x) { return 1.0f / (1.0f + expf(-x)); }

__device__ __forceinline__ unsigned ld_acq(unsigned* p) {
    unsigned v;
    asm volatile("ld.acquire.gpu.u32 %0, [%1];" : "=r"(v) : "l"(p) : "memory");
    return v;
}

// Sense-counting grid barrier. All NB CTAs co-resident (512 CTAs, 4/SM on 128 SMs).
__device__ __forceinline__ void grid_barrier()
{
    __syncthreads();
    if (threadIdx.x == 0) {
        unsigned gen = ld_acq(&g_bar_gen);
        __threadfence();                      // release my writes
        if (atomicAdd(&g_bar_count, 1u) == NB - 1u) {
            g_bar_count = 0u;
            __threadfence();
            atomicAdd(&g_bar_gen, 1u);        // release epoch
        } else {
            while (ld_acq(&g_bar_gen) == gen) __nanosleep(64);
        }
        __threadfence();
    }
    __syncthreads();
}

// ---------------- encoder input gather + transpose (separate pre-kernel) ----------------
__global__ __launch_bounds__(256) void gather_x_kernel(
    const float* __restrict__ emb,
    const int*   __restrict__ tokens,
    int tokStride,
    float* __restrict__ xT)
{
    __shared__ float tile[B][132];
    const int t  = blockIdx.y;
    const int k0 = blockIdx.x * 128;
    const int w = threadIdx.x >> 5, lane = threadIdx.x & 31;

    #pragma unroll
    for (int r = 0; r < 4; r++) {
        int b = w * 4 + r;
        int tokb = tokens[b * tokStride + t];
        float4 v = *(const float4*)(emb + (size_t)tokb * E + k0 + lane * 4);
        tile[b][lane * 4 + 0] = v.x;
        tile[b][lane * 4 + 1] = v.y;
        tile[b][lane * 4 + 2] = v.z;
        tile[b][lane * 4 + 3] = v.w;
    }
    __syncthreads();

    float* out = xT + (size_t)t * E * B + (size_t)k0 * B;
    #pragma unroll
    for (int i = 0; i < 4; i++) {
        int idx = threadIdx.x + i * 256;
        int k   = idx >> 3;
        int b4  = (idx & 7) * 4;
        float4 v = make_float4(tile[b4 + 0][k], tile[b4 + 1][k],
                               tile[b4 + 2][k], tile[b4 + 3][k]);
        *(float4*)(out + k * B + b4) = v;
    }
}

// ---------------- fused LSTM layer phase (gates GEMV + in-CTA cell), ends with grid barrier ----
// CTA c owns columns j in {2c, 2c+1}. Warp w: jl = w&1, gate g = w>>1, row = g*H + j.
__device__ void lstm_layer(
    const float* __restrict__ xT, int KX,
    const float* __restrict__ hT,
    const float* __restrict__ Wih,
    const float* __restrict__ Whh,
    const float* __restrict__ bias,
    float* __restrict__ cT,
    float* __restrict__ hOut,
    float* sx, float* sg)
{
    const int tid = threadIdx.x;
    const int w = tid >> 5, lane = tid & 31;
    const int c = blockIdx.x;
    const int jl = w & 1, g = w >> 1;
    const int j = c * 2 + jl;
    const int row = g * H + j;
    const int KT = KX + H;

    float acc = 0.f;

    for (int kb = 0; kb < KT; kb += 128) {
        const float4* src4 = (kb < KX) ? (const float4*)(xT + (size_t)kb * B)
                                       : (const float4*)(hT + (size_t)(kb - KX) * B);
        float4* s4 = (float4*)sx;
        #pragma unroll
        for (int i = 0; i < 4; i++) s4[tid + i * 256] = src4[tid + i * 256];
        __syncthreads();

        const float* base; int rs, ko;
        if (kb < KX) { base = Wih; rs = KX; ko = kb; }
        else         { base = Whh; rs = H;  ko = kb - KX; }
        const float4* W4 = (const float4*)(base + (size_t)row * rs + ko);

        #pragma unroll
        for (int m = 0; m < 4; m++) {
            float4 wv[8];
            #pragma unroll
            for (int u = 0; u < 8; u++) wv[u] = W4[m * 8 + u];
            #pragma unroll
            for (int u = 0; u < 8; u++) {
                const float* xs = sx + (m * 8 + u) * 128 + lane;
                acc += wv[u].x * xs[0];
                acc += wv[u].y * xs[32];
                acc += wv[u].z * xs[64];
                acc += wv[u].w * xs[96];
            }
        }
        __syncthreads();
    }

    sg[w * 32 + lane] = acc;   // sg index = (g*2 + jl)*32 + lane
    __syncthreads();

    if (tid < 64) {
        int b = tid & 31, jl2 = tid >> 5;
        int jj = c * 2 + jl2;
        float gi = sg[(0 * 2 + jl2) * 32 + b] + bias[0 * H + jj];
        float gf = sg[(1 * 2 + jl2) * 32 + b] + bias[1 * H + jj];
        float gg = sg[(2 * 2 + jl2) * 32 + b] + bias[2 * H + jj];
        float go = sg[(3 * 2 + jl2) * 32 + b] + bias[3 * H + jj];
        float c_old = cT[jj * B + b];
        float c_new = sigm(gf) * c_old + sigm(gi) * tanhf(gg);
        cT[jj * B + b]   = c_new;
        hOut[jj * B + b] = sigm(go) * tanhf(c_new);
    }
    grid_barrier();
}

// ---------------- logits phase: GEMV + bias + store + argmax partials ----------------
__device__ void logits_phase(
    const float* __restrict__ h1T,
    const float* __restrict__ outW,
    const float* __restrict__ outB,
    float* __restrict__ out, int s,
    float* sx, float* sval, int* sidx)
{
    const int tid = threadIdx.x;
    const int w = tid >> 5, lane = tid & 31;
    const int c = blockIdx.x;
    if (c >= LOG_CTAS) return;

    const int vbase = c * 64 + w * 8;
    float acc[8];
    #pragma unroll
    for (int v = 0; v < 8; v++) acc[v] = 0.f;

    for (int kb = 0; kb < H; kb += 128) {
        const float4* src4 = (const float4*)(h1T + (size_t)kb * B);
        float4* s4 = (float4*)sx;
        #pragma unroll
        for (int i = 0; i < 4; i++) s4[tid + i * 256] = src4[tid + i * 256];
        __syncthreads();

        #pragma unroll
        for (int half = 0; half < 2; half++) {
            const float* W0 = outW + (size_t)(vbase + half * 4) * H + kb;
            #pragma unroll 4
            for (int kk = 0; kk < 32; kk++) {
                float4 wv0 = *(const float4*)(W0 + 0 * H + kk * 4);
                float4 wv1 = *(const float4*)(W0 + 1 * H + kk * 4);
                float4 wv2 = *(const float4*)(W0 + 2 * H + kk * 4);
                float4 wv3 = *(const float4*)(W0 + 3 * H + kk * 4);
                const float* xs = sx + kk * 128 + lane;
                float x0 = xs[0], x1 = xs[32], x2 = xs[64], x3 = xs[96];
                acc[half*4+0] += wv0.x * x0; acc[half*4+0] += wv0.y * x1;
                acc[half*4+0] += wv0.z * x2; acc[half*4+0] += wv0.w * x3;
                acc[half*4+1] += wv1.x * x0; acc[half*4+1] += wv1.y * x1;
                acc[half*4+1] += wv1.z * x2; acc[half*4+1] += wv1.w * x3;
                acc[half*4+2] += wv2.x * x0; acc[half*4+2] += wv2.y * x1;
                acc[half*4+2] += wv2.z * x2; acc[half*4+2] += wv2.w * x3;
                acc[half*4+3] += wv3.x * x0; acc[half*4+3] += wv3.y * x1;
                acc[half*4+3] += wv3.z * x2; acc[half*4+3] += wv3.w * x3;
            }
        }
        __syncthreads();
    }

    // bias + vectorized store + per-lane argmax (ascending v => first-index)
    #pragma unroll
    for (int v = 0; v < 8; v++) acc[v] += outB[vbase + v];

    float* orow = out + (size_t)lane * (L * V) + (size_t)s * V + vbase;
    *(float4*)(orow + 0) = make_float4(acc[0], acc[1], acc[2], acc[3]);
    *(float4*)(orow + 4) = make_float4(acc[4], acc[5], acc[6], acc[7]);

    float bv = -INFINITY; int bi = 0;
    #pragma unroll
    for (int v = 0; v < 8; v++)
        if (acc[v] > bv) { bv = acc[v]; bi = vbase + v; }

    sval[w * 32 + lane] = bv;
    sidx[w * 32 + lane] = bi;
    __syncthreads();
    if (w == 0) {
        float BV = sval[lane]; int BI = sidx[lane];
        #pragma unroll
        for (int q = 1; q < 8; q++) {
            float v2 = sval[q * 32 + lane]; int i2 = sidx[q * 32 + lane];
            if (v2 > BV || (v2 == BV && i2 < BI)) { BV = v2; BI = i2; }
        }
        g_pval[c * B + lane] = BV;
        g_pidx[c * B + lane] = BI;
    }
}

// ---------------- argmax final + next-token embedding gather (CTA b = batch b) ---------
__device__ void argmax_gather(const float* __restrict__ emb, bool do_argmax,
                              float* sval, int* sidx)
{
    const int tid = threadIdx.x;
    const int c = blockIdx.x;
    if (c >= B) return;
    const int b = c;
    int tk;

    if (do_argmax) {
        float bv = -INFINITY; int bi = 0x7fffffff;
        for (int idx = tid; idx < LOG_CTAS; idx += 256) {
            float v = g_pval[idx * B + b]; int i = g_pidx[idx * B + b];
            if (v > bv || (v == bv && i < bi)) { bv = v; bi = i; }
        }
        sval[tid] = bv; sidx[tid] = bi;
        __syncthreads();
        for (int off = 128; off; off >>= 1) {
            if (tid < off) {
                float v = sval[tid + off]; int i = sidx[tid + off];
                if (v > sval[tid] || (v == sval[tid] && i < sidx[tid])) {
                    sval[tid] = v; sidx[tid] = i;
                }
            }
            __syncthreads();
        }
        tk = sidx[0];
        if (tid == 0) g_tok[b] = tk;
    } else {
        tk = BOS;
    }

    for (int k = tid; k < E; k += 256)
        g_xdT[k * B + b] = emb[(size_t)tk * E + k];
}

// ---------------- the persistent model kernel ----------------
__global__ __launch_bounds__(256, 4) void model_kernel(
    const float* __restrict__ emb,
    const float* __restrict__ eWih0, const float* __restrict__ eWhh0, const float* __restrict__ eb0,
    const float* __restrict__ eWih1, const float* __restrict__ eWhh1, const float* __restrict__ eb1,
    const float* __restrict__ dWih0, const float* __restrict__ dWhh0, const float* __restrict__ db0,
    const float* __restrict__ dWih1, const float* __restrict__ dWhh1, const float* __restrict__ db1,
    const float* __restrict__ outW,  const float* __restrict__ outB,
    float* __restrict__ out)
{
    __shared__ float sx[128 * B];     // 16 KB activation chunk
    __shared__ float sg[8 * B];       // gate staging for cell
    __shared__ float sval[256];
    __shared__ int   sidx[256];

    const int tid = threadIdx.x;
    const int c = blockIdx.x;

    // ---- init phase ----
    for (int i = c * 256 + tid; i < H * B; i += NB * 256) {
        g_h0T[0][i] = 0.f; g_h1T[0][i] = 0.f;
        g_c0T[i] = 0.f;    g_c1T[i] = 0.f;
    }
    grid_barrier();

    int p0 = 0, p1 = 0;

    // ---- encoder ----
    for (int t = 0; t < T; t++) {
        lstm_layer(g_xsT + (size_t)t * E * B, E, g_h0T[p0],
                   eWih0, eWhh0, eb0, g_c0T, g_h0T[p0 ^ 1], sx, sg);
        p0 ^= 1;
        lstm_layer(g_h0T[p0], H, g_h1T[p1],
                   eWih1, eWhh1, eb1, g_c1T, g_h1T[p1 ^ 1], sx, sg);
        p1 ^= 1;
    }

    // ---- BOS embedding gather for decoder step 0 ----
    argmax_gather(emb, false, sval, sidx);
    grid_barrier();

    // ---- greedy decoder ----
    for (int s = 0; s < L; s++) {
        lstm_layer(g_xdT, E, g_h0T[p0],
                   dWih0, dWhh0, db0, g_c0T, g_h0T[p0 ^ 1], sx, sg);
        p0 ^= 1;
        lstm_layer(g_h0T[p0], H, g_h1T[p1],
                   dWih1, dWhh1, db1, g_c1T, g_h1T[p1 ^ 1], sx, sg);
        p1 ^= 1;
        logits_phase(g_h1T[p1], outW, outB, out, s, sx, sval, sidx);
        grid_barrier();
        argmax_gather(emb, true, sval, sidx);
        grid_barrier();
    }
}

// ---------------- host orchestration: 2 graph nodes total ----------------
extern "C" void kernel_launch(void* const* d_in, const int* in_sizes, int n_in,
                              void* d_out, int out_size)
{
    const int*   src   = (const int*)  d_in[0];
    const float* emb   = (const float*)d_in[1];
    const float* eWih0 = (const float*)d_in[2];
    const float* eWhh0 = (const float*)d_in[3];
    const float* eb0   = (const float*)d_in[4];
    const float* eWih1 = (const float*)d_in[5];
    const float* eWhh1 = (const float*)d_in[6];
    const float* eb1   = (const float*)d_in[7];
    const float* dWih0 = (const float*)d_in[8];
    const float* dWhh0 = (const float*)d_in[9];
    const float* db0   = (const float*)d_in[10];
    const float* dWih1 = (const float*)d_in[11];
    const float* dWhh1 = (const float*)d_in[12];
    const float* db1   = (const float*)d_in[13];
    const float* outW  = (const float*)d_in[14];
    const float* outB  = (const float*)d_in[15];
    float* out = (float*)d_out;

    float* xsT;
    cudaGetSymbolAddress((void**)&xsT, g_xsT);

    gather_x_kernel<<<dim3(E / 128, T), 256>>>(emb, src, T, xsT);

    model_kernel<<<NB, 256>>>(emb,
                              eWih0, eWhh0, eb0, eWih1, eWhh1, eb1,
                              dWih0, dWhh0, db0, dWih1, dWhh1, db1,
                              outW, outB, out);
}

// round 6
// speedup vs baseline: 1.6323x; 1.0015x over previous
#include <cuda_runtime.h>
#include <cuda_bf16.h>
#include <math.h>
#include <stdint.h>

// Problem constants
#define B 32
#define T 128
#define E 512
#define H 1024
#define V 32000
#define L 64
#define BOS 1

#define NB 512            // persistent grid size (CTAs)
#define LOG_CTAS 500      // CTAs doing logits work (64 vocab rows each)

// ---------------- static device scratch ----------------
__device__ float g_xsT[T * E * B];      // encoder inputs [t][k][b]
__device__ float g_xdT[E * B];          // decoder step input [k][b]
__device__ float g_h0T[2][H * B];
__device__ float g_h1T[2][H * B];
__device__ float g_c0T[H * B];
__device__ float g_c1T[H * B];
__device__ int   g_tok[B];
__device__ float g_pval[LOG_CTAS * B];
__device__ int   g_pidx[LOG_CTAS * B];
__device__ unsigned g_bar_count;
__device__ unsigned g_bar_gen;

__device__ __forceinline__ float sigm(float x) { return 1.0f / (1.0f + expf(-x)); }

__device__ __forceinline__ unsigned ld_acq(unsigned* p) {
    unsigned v;
    asm volatile("ld.acquire.gpu.u32 %0, [%1];" : "=r"(v) : "l"(p) : "memory");
    return v;
}

// Sense-counting grid barrier. All NB CTAs co-resident (512 CTAs, 4/SM on 128 SMs).
__device__ __forceinline__ void grid_barrier()
{
    __syncthreads();
    if (threadIdx.x == 0) {
        unsigned gen = ld_acq(&g_bar_gen);
        __threadfence();                      // release my writes
        if (atomicAdd(&g_bar_count, 1u) == NB - 1u) {
            g_bar_count = 0u;
            __threadfence();
            atomicAdd(&g_bar_gen, 1u);        // release epoch
        } else {
            while (ld_acq(&g_bar_gen) == gen) __nanosleep(64);
        }
        __threadfence();
    }
    __syncthreads();
}

// ---------------- encoder input gather + transpose (separate pre-kernel) ----------------
__global__ __launch_bounds__(256) void gather_x_kernel(
    const float* __restrict__ emb,
    const int*   __restrict__ tokens,
    int tokStride,
    float* __restrict__ xT)
{
    __shared__ float tile[B][132];
    const int t  = blockIdx.y;
    const int k0 = blockIdx.x * 128;
    const int w = threadIdx.x >> 5, lane = threadIdx.x & 31;

    #pragma unroll
    for (int r = 0; r < 4; r++) {
        int b = w * 4 + r;
        int tokb = tokens[b * tokStride + t];
        float4 v = *(const float4*)(emb + (size_t)tokb * E + k0 + lane * 4);
        tile[b][lane * 4 + 0] = v.x;
        tile[b][lane * 4 + 1] = v.y;
        tile[b][lane * 4 + 2] = v.z;
        tile[b][lane * 4 + 3] = v.w;
    }
    __syncthreads();

    float* out = xT + (size_t)t * E * B + (size_t)k0 * B;
    #pragma unroll
    for (int i = 0; i < 4; i++) {
        int idx = threadIdx.x + i * 256;
        int k   = idx >> 3;
        int b4  = (idx & 7) * 4;
        float4 v = make_float4(tile[b4 + 0][k], tile[b4 + 1][k],
                               tile[b4 + 2][k], tile[b4 + 3][k]);
        *(float4*)(out + k * B + b4) = v;
    }
}

// ---------------- fused LSTM layer phase (gates GEMV + in-CTA cell), ends with grid barrier ----
// CTA c owns columns j in {2c, 2c+1}. Warp w: jl = w&1, gate g = w>>1, row = g*H + j.
__device__ void lstm_layer(
    const float* __restrict__ xT, int KX,
    const float* __restrict__ hT,
    const float* __restrict__ Wih,
    const float* __restrict__ Whh,
    const float* __restrict__ bias,
    float* __restrict__ cT,
    float* __restrict__ hOut,
    float* sx, float* sg)
{
    const int tid = threadIdx.x;
    const int w = tid >> 5, lane = tid & 31;
    const int c = blockIdx.x;
    const int jl = w & 1, g = w >> 1;
    const int j = c * 2 + jl;
    const int row = g * H + j;
    const int KT = KX + H;

    float acc = 0.f;

    for (int kb = 0; kb < KT; kb += 128) {
        const float4* src4 = (kb < KX) ? (const float4*)(xT + (size_t)kb * B)
                                       : (const float4*)(hT + (size_t)(kb - KX) * B);
        float4* s4 = (float4*)sx;
        #pragma unroll
        for (int i = 0; i < 4; i++) s4[tid + i * 256] = src4[tid + i * 256];
        __syncthreads();

        const float* base; int rs, ko;
        if (kb < KX) { base = Wih; rs = KX; ko = kb; }
        else         { base = Whh; rs = H;  ko = kb - KX; }
        const float4* W4 = (const float4*)(base + (size_t)row * rs + ko);

        #pragma unroll
        for (int m = 0; m < 4; m++) {
            float4 wv[8];
            #pragma unroll
            for (int u = 0; u < 8; u++) wv[u] = W4[m * 8 + u];
            #pragma unroll
            for (int u = 0; u < 8; u++) {
                const float* xs = sx + (m * 8 + u) * 128 + lane;
                acc += wv[u].x * xs[0];
                acc += wv[u].y * xs[32];
                acc += wv[u].z * xs[64];
                acc += wv[u].w * xs[96];
            }
        }
        __syncthreads();
    }

    sg[w * 32 + lane] = acc;   // sg index = (g*2 + jl)*32 + lane
    __syncthreads();

    if (tid < 64) {
        int b = tid & 31, jl2 = tid >> 5;
        int jj = c * 2 + jl2;
        float gi = sg[(0 * 2 + jl2) * 32 + b] + bias[0 * H + jj];
        float gf = sg[(1 * 2 + jl2) * 32 + b] + bias[1 * H + jj];
        float gg = sg[(2 * 2 + jl2) * 32 + b] + bias[2 * H + jj];
        float go = sg[(3 * 2 + jl2) * 32 + b] + bias[3 * H + jj];
        float c_old = cT[jj * B + b];
        float c_new = sigm(gf) * c_old + sigm(gi) * tanhf(gg);
        cT[jj * B + b]   = c_new;
        hOut[jj * B + b] = sigm(go) * tanhf(c_new);
    }
    grid_barrier();
}

// ---------------- logits phase: GEMV + bias + store + argmax partials ----------------
__device__ void logits_phase(
    const float* __restrict__ h1T,
    const float* __restrict__ outW,
    const float* __restrict__ outB,
    float* __restrict__ out, int s,
    float* sx, float* sval, int* sidx)
{
    const int tid = threadIdx.x;
    const int w = tid >> 5, lane = tid & 31;
    const int c = blockIdx.x;
    if (c >= LOG_CTAS) return;

    const int vbase = c * 64 + w * 8;
    float acc[8];
    #pragma unroll
    for (int v = 0; v < 8; v++) acc[v] = 0.f;

    for (int kb = 0; kb < H; kb += 128) {
        const float4* src4 = (const float4*)(h1T + (size_t)kb * B);
        float4* s4 = (float4*)sx;
        #pragma unroll
        for (int i = 0; i < 4; i++) s4[tid + i * 256] = src4[tid + i * 256];
        __syncthreads();

        #pragma unroll
        for (int half = 0; half < 2; half++) {
            const float* W0 = outW + (size_t)(vbase + half * 4) * H + kb;
            #pragma unroll 4
            for (int kk = 0; kk < 32; kk++) {
                float4 wv0 = *(const float4*)(W0 + 0 * H + kk * 4);
                float4 wv1 = *(const float4*)(W0 + 1 * H + kk * 4);
                float4 wv2 = *(const float4*)(W0 + 2 * H + kk * 4);
                float4 wv3 = *(const float4*)(W0 + 3 * H + kk * 4);
                const float* xs = sx + kk * 128 + lane;
                float x0 = xs[0], x1 = xs[32], x2 = xs[64], x3 = xs[96];
                acc[half*4+0] += wv0.x * x0; acc[half*4+0] += wv0.y * x1;
                acc[half*4+0] += wv0.z * x2; acc[half*4+0] += wv0.w * x3;
                acc[half*4+1] += wv1.x * x0; acc[half*4+1] += wv1.y * x1;
                acc[half*4+1] += wv1.z * x2; acc[half*4+1] += wv1.w * x3;
                acc[half*4+2] += wv2.x * x0; acc[half*4+2] += wv2.y * x1;
                acc[half*4+2] += wv2.z * x2; acc[half*4+2] += wv2.w * x3;
                acc[half*4+3] += wv3.x * x0; acc[half*4+3] += wv3.y * x1;
                acc[half*4+3] += wv3.z * x2; acc[half*4+3] += wv3.w * x3;
            }
        }
        __syncthreads();
    }

    // bias + vectorized store + per-lane argmax (ascending v => first-index)
    #pragma unroll
    for (int v = 0; v < 8; v++) acc[v] += outB[vbase + v];

    float* orow = out + (size_t)lane * (L * V) + (size_t)s * V + vbase;
    *(float4*)(orow + 0) = make_float4(acc[0], acc[1], acc[2], acc[3]);
    *(float4*)(orow + 4) = make_float4(acc[4], acc[5], acc[6], acc[7]);

    float bv = -INFINITY; int bi = 0;
    #pragma unroll
    for (int v = 0; v < 8; v++)
        if (acc[v] > bv) { bv = acc[v]; bi = vbase + v; }

    sval[w * 32 + lane] = bv;
    sidx[w * 32 + lane] = bi;
    __syncthreads();
    if (w == 0) {
        float BV = sval[lane]; int BI = sidx[lane];
        #pragma unroll
        for (int q = 1; q < 8; q++) {
            float v2 = sval[q * 32 + lane]; int i2 = sidx[q * 32 + lane];
            if (v2 > BV || (v2 == BV && i2 < BI)) { BV = v2; BI = i2; }
        }
        g_pval[c * B + lane] = BV;
        g_pidx[c * B + lane] = BI;
    }
}

// ---------------- argmax final + next-token embedding gather (CTA b = batch b) ---------
__device__ void argmax_gather(const float* __restrict__ emb, bool do_argmax,
                              float* sval, int* sidx)
{
    const int tid = threadIdx.x;
    const int c = blockIdx.x;
    if (c >= B) return;
    const int b = c;
    int tk;

    if (do_argmax) {
        float bv = -INFINITY; int bi = 0x7fffffff;
        for (int idx = tid; idx < LOG_CTAS; idx += 256) {
            float v = g_pval[idx * B + b]; int i = g_pidx[idx * B + b];
            if (v > bv || (v == bv && i < bi)) { bv = v; bi = i; }
        }
        sval[tid] = bv; sidx[tid] = bi;
        __syncthreads();
        for (int off = 128; off; off >>= 1) {
            if (tid < off) {
                float v = sval[tid + off]; int i = sidx[tid + off];
                if (v > sval[tid] || (v == sval[tid] && i < sidx[tid])) {
                    sval[tid] = v; sidx[tid] = i;
                }
            }
            __syncthreads();
        }
        tk = sidx[0];
        if (tid == 0) g_tok[b] = tk;
    } else {
        tk = BOS;
    }

    for (int k = tid; k < E; k += 256)
        g_xdT[k * B + b] = emb[(size_t)tk * E + k];
}

// ---------------- the persistent model kernel ----------------
__global__ __launch_bounds__(256, 4) void model_kernel(
    const float* __restrict__ emb,
    const float* __restrict__ eWih0, const float* __restrict__ eWhh0, const float* __restrict__ eb0,
    const float* __restrict__ eWih1, const float* __restrict__ eWhh1, const float* __restrict__ eb1,
    const float* __restrict__ dWih0, const float* __restrict__ dWhh0, const float* __restrict__ db0,
    const float* __restrict__ dWih1, const float* __restrict__ dWhh1, const float* __restrict__ db1,
    const float* __restrict__ outW,  const float* __restrict__ outB,
    float* __restrict__ out)
{
    __shared__ float sx[128 * B];     // 16 KB activation chunk
    __shared__ float sg[8 * B];       // gate staging for cell
    __shared__ float sval[256];
    __shared__ int   sidx[256];

    const int tid = threadIdx.x;
    const int c = blockIdx.x;

    // ---- init phase ----
    for (int i = c * 256 + tid; i < H * B; i += NB * 256) {
        g_h0T[0][i] = 0.f; g_h1T[0][i] = 0.f;
        g_c0T[i] = 0.f;    g_c1T[i] = 0.f;
    }
    grid_barrier();

    int p0 = 0, p1 = 0;

    // ---- encoder ----
    for (int t = 0; t < T; t++) {
        lstm_layer(g_xsT + (size_t)t * E * B, E, g_h0T[p0],
                   eWih0, eWhh0, eb0, g_c0T, g_h0T[p0 ^ 1], sx, sg);
        p0 ^= 1;
        lstm_layer(g_h0T[p0], H, g_h1T[p1],
                   eWih1, eWhh1, eb1, g_c1T, g_h1T[p1 ^ 1], sx, sg);
        p1 ^= 1;
    }

    // ---- BOS embedding gather for decoder step 0 ----
    argmax_gather(emb, false, sval, sidx);
    grid_barrier();

    // ---- greedy decoder ----
    for (int s = 0; s < L; s++) {
        lstm_layer(g_xdT, E, g_h0T[p0],
                   dWih0, dWhh0, db0, g_c0T, g_h0T[p0 ^ 1], sx, sg);
        p0 ^= 1;
        lstm_layer(g_h0T[p0], H, g_h1T[p1],
                   dWih1, dWhh1, db1, g_c1T, g_h1T[p1 ^ 1], sx, sg);
        p1 ^= 1;
        logits_phase(g_h1T[p1], outW, outB, out, s, sx, sval, sidx);
        grid_barrier();
        argmax_gather(emb, true, sval, sidx);
        grid_barrier();
    }
}

// ---------------- host orchestration: 2 graph nodes total ----------------
extern "C" void kernel_launch(void* const* d_in, const int* in_sizes, int n_in,
                              void* d_out, int out_size)
{
    const int*   src   = (const int*)  d_in[0];
    const float* emb   = (const float*)d_in[1];
    const float* eWih0 = (const float*)d_in[2];
    const float* eWhh0 = (const float*)d_in[3];
    const float* eb0   = (const float*)d_in[4];
    const float* eWih1 = (const float*)d_in[5];
    const float* eWhh1 = (const float*)d_in[6];
    const float* eb1   = (const float*)d_in[7];
    const float* dWih0 = (const float*)d_in[8];
    const float* dWhh0 = (const float*)d_in[9];
    const float* db0   = (const float*)d_in[10];
    const float* dWih1 = (const float*)d_in[11];
    const float* dWhh1 = (const float*)d_in[12];
    const float* db1   = (const float*)d_in[13];
    const float* outW  = (const float*)d_in[14];
    const float* outB  = (const float*)d_in[15];
    float* out = (float*)d_out;

    float* xsT;
    cudaGetSymbolAddress((void**)&xsT, g_xsT);

    gather_x_kernel<<<dim3(E / 128, T), 256>>>(emb, src, T, xsT);

    model_kernel<<<NB, 256>>>(emb,
                              eWih0, eWhh0, eb0, eWih1, eWhh1, eb1,
                              dWih0, dWhh0, db0, dWih1, dWhh1, db1,
                              outW, outB, out);
}

// round 7
// speedup vs baseline: 1.6323x; 1.0000x over previous
#include <cuda_runtime.h>
#include <cuda_bf16.h>
#include <math.h>
#include <stdint.h>

// Problem constants
#define B 32
#define T 128
#define E 512
#define H 1024
#define V 32000
#define L 64
#define BOS 1

#define NB 512            // persistent grid size (CTAs)
#define LOG_CTAS 500      // CTAs doing logits work (64 vocab rows each)

// ---------------- static device scratch ----------------
__device__ float g_xsT[T * E * B];      // encoder inputs [t][k][b]
__device__ float g_xdT[E * B];          // decoder step input [k][b]
__device__ float g_h0T[2][H * B];
__device__ float g_h1T[2][H * B];
__device__ float g_c0T[H * B];
__device__ float g_c1T[H * B];
__device__ int   g_tok[B];
__device__ float g_pval[LOG_CTAS * B];
__device__ int   g_pidx[LOG_CTAS * B];
__device__ unsigned g_bar_count;
__device__ unsigned g_bar_gen;

__device__ __forceinline__ float sigm(float x) { return 1.0f / (1.0f + expf(-x)); }

__device__ __forceinline__ unsigned ld_acq(unsigned* p) {
    unsigned v;
    asm volatile("ld.acquire.gpu.u32 %0, [%1];" : "=r"(v) : "l"(p) : "memory");
    return v;
}

// Sense-counting grid barrier. All NB CTAs co-resident (512 CTAs, 4/SM on 128 SMs).
__device__ __forceinline__ void grid_barrier()
{
    __syncthreads();
    if (threadIdx.x == 0) {
        unsigned gen = ld_acq(&g_bar_gen);
        __threadfence();                      // release my writes
        if (atomicAdd(&g_bar_count, 1u) == NB - 1u) {
            g_bar_count = 0u;
            __threadfence();
            atomicAdd(&g_bar_gen, 1u);        // release epoch
        } else {
            while (ld_acq(&g_bar_gen) == gen) __nanosleep(64);
        }
        __threadfence();
    }
    __syncthreads();
}

// ---------------- encoder input gather + transpose (separate pre-kernel) ----------------
__global__ __launch_bounds__(256) void gather_x_kernel(
    const float* __restrict__ emb,
    const int*   __restrict__ tokens,
    int tokStride,
    float* __restrict__ xT)
{
    __shared__ float tile[B][132];
    const int t  = blockIdx.y;
    const int k0 = blockIdx.x * 128;
    const int w = threadIdx.x >> 5, lane = threadIdx.x & 31;

    #pragma unroll
    for (int r = 0; r < 4; r++) {
        int b = w * 4 + r;
        int tokb = tokens[b * tokStride + t];
        float4 v = *(const float4*)(emb + (size_t)tokb * E + k0 + lane * 4);
        tile[b][lane * 4 + 0] = v.x;
        tile[b][lane * 4 + 1] = v.y;
        tile[b][lane * 4 + 2] = v.z;
        tile[b][lane * 4 + 3] = v.w;
    }
    __syncthreads();

    float* out = xT + (size_t)t * E * B + (size_t)k0 * B;
    #pragma unroll
    for (int i = 0; i < 4; i++) {
        int idx = threadIdx.x + i * 256;
        int k   = idx >> 3;
        int b4  = (idx & 7) * 4;
        float4 v = make_float4(tile[b4 + 0][k], tile[b4 + 1][k],
                               tile[b4 + 2][k], tile[b4 + 3][k]);
        *(float4*)(out + k * B + b4) = v;
    }
}

// ---------------- fused LSTM layer phase (gates GEMV + in-CTA cell), ends with grid barrier ----
// CTA c owns columns j in {2c, 2c+1}. Warp w: jl = w&1, gate g = w>>1, row = g*H + j.
__device__ void lstm_layer(
    const float* __restrict__ xT, int KX,
    const float* __restrict__ hT,
    const float* __restrict__ Wih,
    const float* __restrict__ Whh,
    const float* __restrict__ bias,
    float* __restrict__ cT,
    float* __restrict__ hOut,
    float* sx, float* sg)
{
    const int tid = threadIdx.x;
    const int w = tid >> 5, lane = tid & 31;
    const int c = blockIdx.x;
    const int jl = w & 1, g = w >> 1;
    const int j = c * 2 + jl;
    const int row = g * H + j;
    const int KT = KX + H;

    float acc = 0.f;

    for (int kb = 0; kb < KT; kb += 128) {
        const float4* src4 = (kb < KX) ? (const float4*)(xT + (size_t)kb * B)
                                       : (const float4*)(hT + (size_t)(kb - KX) * B);
        float4* s4 = (float4*)sx;
        #pragma unroll
        for (int i = 0; i < 4; i++) s4[tid + i * 256] = src4[tid + i * 256];
        __syncthreads();

        const float* base; int rs, ko;
        if (kb < KX) { base = Wih; rs = KX; ko = kb; }
        else         { base = Whh; rs = H;  ko = kb - KX; }
        const float4* W4 = (const float4*)(base + (size_t)row * rs + ko);

        #pragma unroll
        for (int m = 0; m < 4; m++) {
            float4 wv[8];
            #pragma unroll
            for (int u = 0; u < 8; u++) wv[u] = W4[m * 8 + u];
            #pragma unroll
            for (int u = 0; u < 8; u++) {
                const float* xs = sx + (m * 8 + u) * 128 + lane;
                acc += wv[u].x * xs[0];
                acc += wv[u].y * xs[32];
                acc += wv[u].z * xs[64];
                acc += wv[u].w * xs[96];
            }
        }
        __syncthreads();
    }

    sg[w * 32 + lane] = acc;   // sg index = (g*2 + jl)*32 + lane
    __syncthreads();

    if (tid < 64) {
        int b = tid & 31, jl2 = tid >> 5;
        int jj = c * 2 + jl2;
        float gi = sg[(0 * 2 + jl2) * 32 + b] + bias[0 * H + jj];
        float gf = sg[(1 * 2 + jl2) * 32 + b] + bias[1 * H + jj];
        float gg = sg[(2 * 2 + jl2) * 32 + b] + bias[2 * H + jj];
        float go = sg[(3 * 2 + jl2) * 32 + b] + bias[3 * H + jj];
        float c_old = cT[jj * B + b];
        float c_new = sigm(gf) * c_old + sigm(gi) * tanhf(gg);
        cT[jj * B + b]   = c_new;
        hOut[jj * B + b] = sigm(go) * tanhf(c_new);
    }
    grid_barrier();
}

// ---------------- logits phase: GEMV + bias + store + argmax partials ----------------
__device__ void logits_phase(
    const float* __restrict__ h1T,
    const float* __restrict__ outW,
    const float* __restrict__ outB,
    float* __restrict__ out, int s,
    float* sx, float* sval, int* sidx)
{
    const int tid = threadIdx.x;
    const int w = tid >> 5, lane = tid & 31;
    const int c = blockIdx.x;
    if (c >= LOG_CTAS) return;

    const int vbase = c * 64 + w * 8;
    float acc[8];
    #pragma unroll
    for (int v = 0; v < 8; v++) acc[v] = 0.f;

    for (int kb = 0; kb < H; kb += 128) {
        const float4* src4 = (const float4*)(h1T + (size_t)kb * B);
        float4* s4 = (float4*)sx;
        #pragma unroll
        for (int i = 0; i < 4; i++) s4[tid + i * 256] = src4[tid + i * 256];
        __syncthreads();

        #pragma unroll
        for (int half = 0; half < 2; half++) {
            const float* W0 = outW + (size_t)(vbase + half * 4) * H + kb;
            #pragma unroll 4
            for (int kk = 0; kk < 32; kk++) {
                float4 wv0 = *(const float4*)(W0 + 0 * H + kk * 4);
                float4 wv1 = *(const float4*)(W0 + 1 * H + kk * 4);
                float4 wv2 = *(const float4*)(W0 + 2 * H + kk * 4);
                float4 wv3 = *(const float4*)(W0 + 3 * H + kk * 4);
                const float* xs = sx + kk * 128 + lane;
                float x0 = xs[0], x1 = xs[32], x2 = xs[64], x3 = xs[96];
                acc[half*4+0] += wv0.x * x0; acc[half*4+0] += wv0.y * x1;
                acc[half*4+0] += wv0.z * x2; acc[half*4+0] += wv0.w * x3;
                acc[half*4+1] += wv1.x * x0; acc[half*4+1] += wv1.y * x1;
                acc[half*4+1] += wv1.z * x2; acc[half*4+1] += wv1.w * x3;
                acc[half*4+2] += wv2.x * x0; acc[half*4+2] += wv2.y * x1;
                acc[half*4+2] += wv2.z * x2; acc[half*4+2] += wv2.w * x3;
                acc[half*4+3] += wv3.x * x0; acc[half*4+3] += wv3.y * x1;
                acc[half*4+3] += wv3.z * x2; acc[half*4+3] += wv3.w * x3;
            }
        }
        __syncthreads();
    }

    // bias + vectorized store + per-lane argmax (ascending v => first-index)
    #pragma unroll
    for (int v = 0; v < 8; v++) acc[v] += outB[vbase + v];

    float* orow = out + (size_t)lane * (L * V) + (size_t)s * V + vbase;
    *(float4*)(orow + 0) = make_float4(acc[0], acc[1], acc[2], acc[3]);
    *(float4*)(orow + 4) = make_float4(acc[4], acc[5], acc[6], acc[7]);

    float bv = -INFINITY; int bi = 0;
    #pragma unroll
    for (int v = 0; v < 8; v++)
        if (acc[v] > bv) { bv = acc[v]; bi = vbase + v; }

    sval[w * 32 + lane] = bv;
    sidx[w * 32 + lane] = bi;
    __syncthreads();
    if (w == 0) {
        float BV = sval[lane]; int BI = sidx[lane];
        #pragma unroll
        for (int q = 1; q < 8; q++) {
            float v2 = sval[q * 32 + lane]; int i2 = sidx[q * 32 + lane];
            if (v2 > BV || (v2 == BV && i2 < BI)) { BV = v2; BI = i2; }
        }
        g_pval[c * B + lane] = BV;
        g_pidx[c * B + lane] = BI;
    }
}

// ---------------- argmax final + next-token embedding gather (CTA b = batch b) ---------
__device__ void argmax_gather(const float* __restrict__ emb, bool do_argmax,
                              float* sval, int* sidx)
{
    const int tid = threadIdx.x;
    const int c = blockIdx.x;
    if (c >= B) return;
    const int b = c;
    int tk;

    if (do_argmax) {
        float bv = -INFINITY; int bi = 0x7fffffff;
        for (int idx = tid; idx < LOG_CTAS; idx += 256) {
            float v = g_pval[idx * B + b]; int i = g_pidx[idx * B + b];
            if (v > bv || (v == bv && i < bi)) { bv = v; bi = i; }
        }
        sval[tid] = bv; sidx[tid] = bi;
        __syncthreads();
        for (int off = 128; off; off >>= 1) {
            if (tid < off) {
                float v = sval[tid + off]; int i = sidx[tid + off];
                if (v > sval[tid] || (v == sval[tid] && i < sidx[tid])) {
                    sval[tid] = v; sidx[tid] = i;
                }
            }
            __syncthreads();
        }
        tk = sidx[0];
        if (tid == 0) g_tok[b] = tk;
    } else {
        tk = BOS;
    }

    for (int k = tid; k < E; k += 256)
        g_xdT[k * B + b] = emb[(size_t)tk * E + k];
}

// ---------------- the persistent model kernel ----------------
__global__ __launch_bounds__(256, 4) void model_kernel(
    const float* __restrict__ emb,
    const float* __restrict__ eWih0, const float* __restrict__ eWhh0, const float* __restrict__ eb0,
    const float* __restrict__ eWih1, const float* __restrict__ eWhh1, const float* __restrict__ eb1,
    const float* __restrict__ dWih0, const float* __restrict__ dWhh0, const float* __restrict__ db0,
    const float* __restrict__ dWih1, const float* __restrict__ dWhh1, const float* __restrict__ db1,
    const float* __restrict__ outW,  const float* __restrict__ outB,
    float* __restrict__ out)
{
    __shared__ float sx[128 * B];     // 16 KB activation chunk
    __shared__ float sg[8 * B];       // gate staging for cell
    __shared__ float sval[256];
    __shared__ int   sidx[256];

    const int tid = threadIdx.x;
    const int c = blockIdx.x;

    // ---- init phase ----
    for (int i = c * 256 + tid; i < H * B; i += NB * 256) {
        g_h0T[0][i] = 0.f; g_h1T[0][i] = 0.f;
        g_c0T[i] = 0.f;    g_c1T[i] = 0.f;
    }
    grid_barrier();

    int p0 = 0, p1 = 0;

    // ---- encoder ----
    for (int t = 0; t < T; t++) {
        lstm_layer(g_xsT + (size_t)t * E * B, E, g_h0T[p0],
                   eWih0, eWhh0, eb0, g_c0T, g_h0T[p0 ^ 1], sx, sg);
        p0 ^= 1;
        lstm_layer(g_h0T[p0], H, g_h1T[p1],
                   eWih1, eWhh1, eb1, g_c1T, g_h1T[p1 ^ 1], sx, sg);
        p1 ^= 1;
    }

    // ---- BOS embedding gather for decoder step 0 ----
    argmax_gather(emb, false, sval, sidx);
    grid_barrier();

    // ---- greedy decoder ----
    for (int s = 0; s < L; s++) {
        lstm_layer(g_xdT, E, g_h0T[p0],
                   dWih0, dWhh0, db0, g_c0T, g_h0T[p0 ^ 1], sx, sg);
        p0 ^= 1;
        lstm_layer(g_h0T[p0], H, g_h1T[p1],
                   dWih1, dWhh1, db1, g_c1T, g_h1T[p1 ^ 1], sx, sg);
        p1 ^= 1;
        logits_phase(g_h1T[p1], outW, outB, out, s, sx, sval, sidx);
        grid_barrier();
        argmax_gather(emb, true, sval, sidx);
        grid_barrier();
    }
}

// ---------------- host orchestration: 2 graph nodes total ----------------
extern "C" void kernel_launch(void* const* d_in, const int* in_sizes, int n_in,
                              void* d_out, int out_size)
{
    const int*   src   = (const int*)  d_in[0];
    const float* emb   = (const float*)d_in[1];
    const float* eWih0 = (const float*)d_in[2];
    const float* eWhh0 = (const float*)d_in[3];
    const float* eb0   = (const float*)d_in[4];
    const float* eWih1 = (const float*)d_in[5];
    const float* eWhh1 = (const float*)d_in[6];
    const float* eb1   = (const float*)d_in[7];
    const float* dWih0 = (const float*)d_in[8];
    const float* dWhh0 = (const float*)d_in[9];
    const float* db0   = (const float*)d_in[10];
    const float* dWih1 = (const float*)d_in[11];
    const float* dWhh1 = (const float*)d_in[12];
    const float* db1   = (const float*)d_in[13];
    const float* outW  = (const float*)d_in[14];
    const float* outB  = (const float*)d_in[15];
    float* out = (float*)d_out;

    float* xsT;
    cudaGetSymbolAddress((void**)&xsT, g_xsT);

    gather_x_kernel<<<dim3(E / 128, T), 256>>>(emb, src, T, xsT);

    model_kernel<<<NB, 256>>>(emb,
                              eWih0, eWhh0, eb0, eWih1, eWhh1, eb1,
                              dWih0, dWhh0, db0, dWih1, dWhh1, db1,
                              outW, outB, out);
}

// round 8
// speedup vs baseline: 1.6323x; 1.0000x over previous
#include <cuda_runtime.h>
#include <cuda_bf16.h>
#include <math.h>
#include <stdint.h>

// Problem constants
#define B 32
#define T 128
#define E 512
#define H 1024
#define V 32000
#define L 64
#define BOS 1

#define NB 512            // persistent grid size (CTAs)
#define LOG_CTAS 500      // CTAs doing logits work (64 vocab rows each)

// ---------------- static device scratch ----------------
__device__ float g_xsT[T * E * B];      // encoder inputs [t][k][b]
__device__ float g_xdT[E * B];          // decoder step input [k][b]
__device__ float g_h0T[2][H * B];
__device__ float g_h1T[2][H * B];
__device__ float g_c0T[H * B];
__device__ float g_c1T[H * B];
__device__ int   g_tok[B];
__device__ float g_pval[LOG_CTAS * B];
__device__ int   g_pidx[LOG_CTAS * B];
__device__ unsigned g_bar_count;
__device__ unsigned g_bar_gen;

__device__ __forceinline__ float sigm(float x) { return 1.0f / (1.0f + expf(-x)); }

__device__ __forceinline__ unsigned ld_acq(unsigned* p) {
    unsigned v;
    asm volatile("ld.acquire.gpu.u32 %0, [%1];" : "=r"(v) : "l"(p) : "memory");
    return v;
}

// Sense-counting grid barrier. All NB CTAs co-resident (512 CTAs, 4/SM on 128 SMs).
__device__ __forceinline__ void grid_barrier()
{
    __syncthreads();
    if (threadIdx.x == 0) {
        unsigned gen = ld_acq(&g_bar_gen);
        __threadfence();                      // release my writes
        if (atomicAdd(&g_bar_count, 1u) == NB - 1u) {
            g_bar_count = 0u;
            __threadfence();
            atomicAdd(&g_bar_gen, 1u);        // release epoch
        } else {
            while (ld_acq(&g_bar_gen) == gen) __nanosleep(64);
        }
        __threadfence();
    }
    __syncthreads();
}

// ---------------- encoder input gather + transpose (separate pre-kernel) ----------------
__global__ __launch_bounds__(256) void gather_x_kernel(
    const float* __restrict__ emb,
    const int*   __restrict__ tokens,
    int tokStride,
    float* __restrict__ xT)
{
    __shared__ float tile[B][132];
    const int t  = blockIdx.y;
    const int k0 = blockIdx.x * 128;
    const int w = threadIdx.x >> 5, lane = threadIdx.x & 31;

    #pragma unroll
    for (int r = 0; r < 4; r++) {
        int b = w * 4 + r;
        int tokb = tokens[b * tokStride + t];
        float4 v = *(const float4*)(emb + (size_t)tokb * E + k0 + lane * 4);
        tile[b][lane * 4 + 0] = v.x;
        tile[b][lane * 4 + 1] = v.y;
        tile[b][lane * 4 + 2] = v.z;
        tile[b][lane * 4 + 3] = v.w;
    }
    __syncthreads();

    float* out = xT + (size_t)t * E * B + (size_t)k0 * B;
    #pragma unroll
    for (int i = 0; i < 4; i++) {
        int idx = threadIdx.x + i * 256;
        int k   = idx >> 3;
        int b4  = (idx & 7) * 4;
        float4 v = make_float4(tile[b4 + 0][k], tile[b4 + 1][k],
                               tile[b4 + 2][k], tile[b4 + 3][k]);
        *(float4*)(out + k * B + b4) = v;
    }
}

// ---------------- fused LSTM layer phase (gates GEMV + in-CTA cell), ends with grid barrier ----
// CTA c owns columns j in {2c, 2c+1}. Warp w: jl = w&1, gate g = w>>1, row = g*H + j.
__device__ void lstm_layer(
    const float* __restrict__ xT, int KX,
    const float* __restrict__ hT,
    const float* __restrict__ Wih,
    const float* __restrict__ Whh,
    const float* __restrict__ bias,
    float* __restrict__ cT,
    float* __restrict__ hOut,
    float* sx, float* sg)
{
    const int tid = threadIdx.x;
    const int w = tid >> 5, lane = tid & 31;
    const int c = blockIdx.x;
    const int jl = w & 1, g = w >> 1;
    const int j = c * 2 + jl;
    const int row = g * H + j;
    const int KT = KX + H;

    float acc = 0.f;

    for (int kb = 0; kb < KT; kb += 128) {
        const float4* src4 = (kb < KX) ? (const float4*)(xT + (size_t)kb * B)
                                       : (const float4*)(hT + (size_t)(kb - KX) * B);
        float4* s4 = (float4*)sx;
        #pragma unroll
        for (int i = 0; i < 4; i++) s4[tid + i * 256] = src4[tid + i * 256];
        __syncthreads();

        const float* base; int rs, ko;
        if (kb < KX) { base = Wih; rs = KX; ko = kb; }
        else         { base = Whh; rs = H;  ko = kb - KX; }
        const float4* W4 = (const float4*)(base + (size_t)row * rs + ko);

        #pragma unroll
        for (int m = 0; m < 4; m++) {
            float4 wv[8];
            #pragma unroll
            for (int u = 0; u < 8; u++) wv[u] = W4[m * 8 + u];
            #pragma unroll
            for (int u = 0; u < 8; u++) {
                const float* xs = sx + (m * 8 + u) * 128 + lane;
                acc += wv[u].x * xs[0];
                acc += wv[u].y * xs[32];
                acc += wv[u].z * xs[64];
                acc += wv[u].w * xs[96];
            }
        }
        __syncthreads();
    }

    sg[w * 32 + lane] = acc;   // sg index = (g*2 + jl)*32 + lane
    __syncthreads();

    if (tid < 64) {
        int b = tid & 31, jl2 = tid >> 5;
        int jj = c * 2 + jl2;
        float gi = sg[(0 * 2 + jl2) * 32 + b] + bias[0 * H + jj];
        float gf = sg[(1 * 2 + jl2) * 32 + b] + bias[1 * H + jj];
        float gg = sg[(2 * 2 + jl2) * 32 + b] + bias[2 * H + jj];
        float go = sg[(3 * 2 + jl2) * 32 + b] + bias[3 * H + jj];
        float c_old = cT[jj * B + b];
        float c_new = sigm(gf) * c_old + sigm(gi) * tanhf(gg);
        cT[jj * B + b]   = c_new;
        hOut[jj * B + b] = sigm(go) * tanhf(c_new);
    }
    grid_barrier();
}

// ---------------- logits phase: GEMV + bias + store + argmax partials ----------------
__device__ void logits_phase(
    const float* __restrict__ h1T,
    const float* __restrict__ outW,
    const float* __restrict__ outB,
    float* __restrict__ out, int s,
    float* sx, float* sval, int* sidx)
{
    const int tid = threadIdx.x;
    const int w = tid >> 5, lane = tid & 31;
    const int c = blockIdx.x;
    if (c >= LOG_CTAS) return;

    const int vbase = c * 64 + w * 8;
    float acc[8];
    #pragma unroll
    for (int v = 0; v < 8; v++) acc[v] = 0.f;

    for (int kb = 0; kb < H; kb += 128) {
        const float4* src4 = (const float4*)(h1T + (size_t)kb * B);
        float4* s4 = (float4*)sx;
        #pragma unroll
        for (int i = 0; i < 4; i++) s4[tid + i * 256] = src4[tid + i * 256];
        __syncthreads();

        #pragma unroll
        for (int half = 0; half < 2; half++) {
            const float* W0 = outW + (size_t)(vbase + half * 4) * H + kb;
            #pragma unroll 4
            for (int kk = 0; kk < 32; kk++) {
                float4 wv0 = *(const float4*)(W0 + 0 * H + kk * 4);
                float4 wv1 = *(const float4*)(W0 + 1 * H + kk * 4);
                float4 wv2 = *(const float4*)(W0 + 2 * H + kk * 4);
                float4 wv3 = *(const float4*)(W0 + 3 * H + kk * 4);
                const float* xs = sx + kk * 128 + lane;
                float x0 = xs[0], x1 = xs[32], x2 = xs[64], x3 = xs[96];
                acc[half*4+0] += wv0.x * x0; acc[half*4+0] += wv0.y * x1;
                acc[half*4+0] += wv0.z * x2; acc[half*4+0] += wv0.w * x3;
                acc[half*4+1] += wv1.x * x0; acc[half*4+1] += wv1.y * x1;
                acc[half*4+1] += wv1.z * x2; acc[half*4+1] += wv1.w * x3;
                acc[half*4+2] += wv2.x * x0; acc[half*4+2] += wv2.y * x1;
                acc[half*4+2] += wv2.z * x2; acc[half*4+2] += wv2.w * x3;
                acc[half*4+3] += wv3.x * x0; acc[half*4+3] += wv3.y * x1;
                acc[half*4+3] += wv3.z * x2; acc[half*4+3] += wv3.w * x3;
            }
        }
        __syncthreads();
    }

    // bias + vectorized store + per-lane argmax (ascending v => first-index)
    #pragma unroll
    for (int v = 0; v < 8; v++) acc[v] += outB[vbase + v];

    float* orow = out + (size_t)lane * (L * V) + (size_t)s * V + vbase;
    *(float4*)(orow + 0) = make_float4(acc[0], acc[1], acc[2], acc[3]);
    *(float4*)(orow + 4) = make_float4(acc[4], acc[5], acc[6], acc[7]);

    float bv = -INFINITY; int bi = 0;
    #pragma unroll
    for (int v = 0; v < 8; v++)
        if (acc[v] > bv) { bv = acc[v]; bi = vbase + v; }

    sval[w * 32 + lane] = bv;
    sidx[w * 32 + lane] = bi;
    __syncthreads();
    if (w == 0) {
        float BV = sval[lane]; int BI = sidx[lane];
        #pragma unroll
        for (int q = 1; q < 8; q++) {
            float v2 = sval[q * 32 + lane]; int i2 = sidx[q * 32 + lane];
            if (v2 > BV || (v2 == BV && i2 < BI)) { BV = v2; BI = i2; }
        }
        g_pval[c * B + lane] = BV;
        g_pidx[c * B + lane] = BI;
    }
}

// ---------------- argmax final + next-token embedding gather (CTA b = batch b) ---------
__device__ void argmax_gather(const float* __restrict__ emb, bool do_argmax,
                              float* sval, int* sidx)
{
    const int tid = threadIdx.x;
    const int c = blockIdx.x;
    if (c >= B) return;
    const int b = c;
    int tk;

    if (do_argmax) {
        float bv = -INFINITY; int bi = 0x7fffffff;
        for (int idx = tid; idx < LOG_CTAS; idx += 256) {
            float v = g_pval[idx * B + b]; int i = g_pidx[idx * B + b];
            if (v > bv || (v == bv && i < bi)) { bv = v; bi = i; }
        }
        sval[tid] = bv; sidx[tid] = bi;
        __syncthreads();
        for (int off = 128; off; off >>= 1) {
            if (tid < off) {
                float v = sval[tid + off]; int i = sidx[tid + off];
                if (v > sval[tid] || (v == sval[tid] && i < sidx[tid])) {
                    sval[tid] = v; sidx[tid] = i;
                }
            }
            __syncthreads();
        }
        tk = sidx[0];
        if (tid == 0) g_tok[b] = tk;
    } else {
        tk = BOS;
    }

    for (int k = tid; k < E; k += 256)
        g_xdT[k * B + b] = emb[(size_t)tk * E + k];
}

// ---------------- the persistent model kernel ----------------
__global__ __launch_bounds__(256, 4) void model_kernel(
    const float* __restrict__ emb,
    const float* __restrict__ eWih0, const float* __restrict__ eWhh0, const float* __restrict__ eb0,
    const float* __restrict__ eWih1, const float* __restrict__ eWhh1, const float* __restrict__ eb1,
    const float* __restrict__ dWih0, const float* __restrict__ dWhh0, const float* __restrict__ db0,
    const float* __restrict__ dWih1, const float* __restrict__ dWhh1, const float* __restrict__ db1,
    const float* __restrict__ outW,  const float* __restrict__ outB,
    float* __restrict__ out)
{
    __shared__ float sx[128 * B];     // 16 KB activation chunk
    __shared__ float sg[8 * B];       // gate staging for cell
    __shared__ float sval[256];
    __shared__ int   sidx[256];

    const int tid = threadIdx.x;
    const int c = blockIdx.x;

    // ---- init phase ----
    for (int i = c * 256 + tid; i < H * B; i += NB * 256) {
        g_h0T[0][i] = 0.f; g_h1T[0][i] = 0.f;
        g_c0T[i] = 0.f;    g_c1T[i] = 0.f;
    }
    grid_barrier();

    int p0 = 0, p1 = 0;

    // ---- encoder ----
    for (int t = 0; t < T; t++) {
        lstm_layer(g_xsT + (size_t)t * E * B, E, g_h0T[p0],
                   eWih0, eWhh0, eb0, g_c0T, g_h0T[p0 ^ 1], sx, sg);
        p0 ^= 1;
        lstm_layer(g_h0T[p0], H, g_h1T[p1],
                   eWih1, eWhh1, eb1, g_c1T, g_h1T[p1 ^ 1], sx, sg);
        p1 ^= 1;
    }

    // ---- BOS embedding gather for decoder step 0 ----
    argmax_gather(emb, false, sval, sidx);
    grid_barrier();

    // ---- greedy decoder ----
    for (int s = 0; s < L; s++) {
        lstm_layer(g_xdT, E, g_h0T[p0],
                   dWih0, dWhh0, db0, g_c0T, g_h0T[p0 ^ 1], sx, sg);
        p0 ^= 1;
        lstm_layer(g_h0T[p0], H, g_h1T[p1],
                   dWih1, dWhh1, db1, g_c1T, g_h1T[p1 ^ 1], sx, sg);
        p1 ^= 1;
        logits_phase(g_h1T[p1], outW, outB, out, s, sx, sval, sidx);
        grid_barrier();
        argmax_gather(emb, true, sval, sidx);
        grid_barrier();
    }
}

// ---------------- host orchestration: 2 graph nodes total ----------------
extern "C" void kernel_launch(void* const* d_in, const int* in_sizes, int n_in,
                              void* d_out, int out_size)
{
    const int*   src   = (const int*)  d_in[0];
    const float* emb   = (const float*)d_in[1];
    const float* eWih0 = (const float*)d_in[2];
    const float* eWhh0 = (const float*)d_in[3];
    const float* eb0   = (const float*)d_in[4];
    const float* eWih1 = (const float*)d_in[5];
    const float* eWhh1 = (const float*)d_in[6];
    const float* eb1   = (const float*)d_in[7];
    const float* dWih0 = (const float*)d_in[8];
    const float* dWhh0 = (const float*)d_in[9];
    const float* db0   = (const float*)d_in[10];
    const float* dWih1 = (const float*)d_in[11];
    const float* dWhh1 = (const float*)d_in[12];
    const float* db1   = (const float*)d_in[13];
    const float* outW  = (const float*)d_in[14];
    const float* outB  = (const float*)d_in[15];
    float* out = (float*)d_out;

    float* xsT;
    cudaGetSymbolAddress((void**)&xsT, g_xsT);

    gather_x_kernel<<<dim3(E / 128, T), 256>>>(emb, src, T, xsT);

    model_kernel<<<NB, 256>>>(emb,
                              eWih0, eWhh0, eb0, eWih1, eWhh1, eb1,
                              dWih0, dWhh0, db0, dWih1, dWhh1, db1,
                              outW, outB, out);
}

// round 9
// speedup vs baseline: 3.0941x; 1.8955x over previous
#include <cuda_runtime.h>
#include <math.h>
#include <stdint.h>

#define B 32
#define T 128
#define E 512
#define H 1024
#define V 32000
#define L 64
#define BOS 1
#define NB 512
#define R4H 4096
#define NSLICE 16
#define LCTAS 500

// ---------------- static device scratch ----------------
__device__ float g_xsT[T * E * B];
__device__ float g_xdT[E * B];
__device__ float g_h0T[2][H * B];
__device__ float g_h1T[2][H * B];
__device__ float g_c0T[H * B];
__device__ float g_c1T[H * B];
__device__ float g_part[NSLICE * R4H * B];    // split-K gate partials
__device__ float g_pval[LCTAS * B];
__device__ int   g_pidx[LCTAS * B];
__device__ unsigned g_bar_count, g_bar_gen;

// transposed weights: WT[k][row]
__device__ float g_WTe0[(E + H) * R4H];
__device__ float g_WTe1[(H + H) * R4H];
__device__ float g_WTd0[(E + H) * R4H];
__device__ float g_WTd1[(H + H) * R4H];
__device__ float g_outWT[H * V];              // [k][v]

__device__ __forceinline__ float sigm(float x) { return 1.0f / (1.0f + expf(-x)); }

#define PACKXX(d, f)  asm("mov.b64 %0, {%1,%1};" : "=l"(d) : "f"(f))
#define FMA2(acc, a, b) asm("fma.rn.f32x2 %0, %1, %2, %0;" : "+l"(acc) : "l"(a), "l"(b))
#define ADD2(d, a, b) asm("add.rn.f32x2 %0, %1, %2;" : "=l"(d) : "l"(a), "l"(b))
#define UNPACK2(lo, hi, v) asm("mov.b64 {%0,%1}, %2;" : "=f"(lo), "=f"(hi) : "l"(v))

__device__ __forceinline__ unsigned ld_acq(unsigned* p) {
    unsigned v;
    asm volatile("ld.acquire.gpu.u32 %0, [%1];" : "=r"(v) : "l"(p) : "memory");
    return v;
}

// Sense-counting grid barrier (all NB CTAs co-resident).
__device__ __forceinline__ void grid_barrier()
{
    __syncthreads();
    if (threadIdx.x == 0) {
        unsigned gen = ld_acq(&g_bar_gen);
        __threadfence();
        if (atomicAdd(&g_bar_count, 1u) == NB - 1u) {
            g_bar_count = 0u;
            __threadfence();
            atomicAdd(&g_bar_gen, 1u);
        } else {
            while (ld_acq(&g_bar_gen) == gen) __nanosleep(64);
        }
        __threadfence();
    }
    __syncthreads();
}

// ---------------- pre-kernels ----------------
// transpose: in[R][C] row-major -> out[(c+koff)][r] with row stride OS
__global__ __launch_bounds__(256) void transpose_kernel(
    const float* __restrict__ in, float* __restrict__ out,
    int C, int OS, int koff)
{
    __shared__ float t[32][33];
    const int tx = threadIdx.x & 31, ty = threadIdx.x >> 5;
    const int r0 = blockIdx.y * 32, c0 = blockIdx.x * 32;
    #pragma unroll
    for (int i = 0; i < 4; i++)
        t[ty + 8 * i][tx] = in[(size_t)(r0 + ty + 8 * i) * C + (c0 + tx)];
    __syncthreads();
    #pragma unroll
    for (int i = 0; i < 4; i++)
        out[(size_t)(c0 + koff + ty + 8 * i) * OS + (r0 + tx)] = t[tx][ty + 8 * i];
}

__global__ __launch_bounds__(256) void gather_x_kernel(
    const float* __restrict__ emb,
    const int*   __restrict__ tokens,
    int tokStride, float* __restrict__ xT)
{
    __shared__ float tile[B][132];
    const int t  = blockIdx.y;
    const int k0 = blockIdx.x * 128;
    const int w = threadIdx.x >> 5, lane = threadIdx.x & 31;
    #pragma unroll
    for (int r = 0; r < 4; r++) {
        int b = w * 4 + r;
        int tokb = tokens[b * tokStride + t];
        float4 v = *(const float4*)(emb + (size_t)tokb * E + k0 + lane * 4);
        tile[b][lane * 4 + 0] = v.x; tile[b][lane * 4 + 1] = v.y;
        tile[b][lane * 4 + 2] = v.z; tile[b][lane * 4 + 3] = v.w;
    }
    __syncthreads();
    float* out = xT + (size_t)t * E * B + (size_t)k0 * B;
    #pragma unroll
    for (int i = 0; i < 4; i++) {
        int idx = threadIdx.x + i * 256;
        int k = idx >> 3, b4 = (idx & 7) * 4;
        *(float4*)(out + k * B + b4) = make_float4(tile[b4+0][k], tile[b4+1][k],
                                                   tile[b4+2][k], tile[b4+3][k]);
    }
}

// ---------------- gates: warp = 32 rows x 16 batches, split-K 16 ----------------
__device__ __forceinline__ void mac_range(
    unsigned long long acc[2][4],
    const float* __restrict__ WT,
    const float* __restrict__ src, int srcoff,
    int myrow, int bcol, int k0, int k1)
{
    const float* wp = WT + (size_t)k0 * R4H + myrow;
    const float* xp = src + (size_t)(k0 - srcoff) * B + bcol;
    #pragma unroll 4
    for (int k = k0; k < k1; k++) {
        ulonglong2 w2 = *(const ulonglong2*)wp;    // rows (r0,r1),(r2,r3) packed
        float4 x4 = *(const float4*)xp;
        unsigned long long xx;
        PACKXX(xx, x4.x); FMA2(acc[0][0], w2.x, xx); FMA2(acc[1][0], w2.y, xx);
        PACKXX(xx, x4.y); FMA2(acc[0][1], w2.x, xx); FMA2(acc[1][1], w2.y, xx);
        PACKXX(xx, x4.z); FMA2(acc[0][2], w2.x, xx); FMA2(acc[1][2], w2.y, xx);
        PACKXX(xx, x4.w); FMA2(acc[0][3], w2.x, xx); FMA2(acc[1][3], w2.y, xx);
        wp += R4H; xp += B;
    }
}

__device__ void gates_phase(const float* __restrict__ xT, int KX,
                            const float* __restrict__ hT,
                            const float* __restrict__ WT, int KT)
{
    const int gw = blockIdx.x * 8 + (threadIdx.x >> 5);   // 0..4095
    const int lane = threadIdx.x & 31;
    const int s = gw & (NSLICE - 1);
    const int pos = gw >> 4;                              // 0..255
    const int bh = pos & 1, rg = pos >> 1;
    const int myrow = rg * 32 + (lane >> 2) * 4;
    const int bcol  = bh * 16 + (lane & 3) * 4;
    const int KS = KT / NSLICE;
    const int klo = s * KS, khi = klo + KS;

    unsigned long long acc[2][4];
    #pragma unroll
    for (int a = 0; a < 2; a++)
        #pragma unroll
        for (int b = 0; b < 4; b++) acc[a][b] = 0ull;

    int kxe = khi < KX ? khi : KX;
    if (klo < KX) mac_range(acc, WT, xT, 0, myrow, bcol, klo, kxe);
    int khs = klo > KX ? klo : KX;
    if (khi > KX) mac_range(acc, WT, hT, KX, myrow, bcol, khs, khi);

    float vr[4][4];
    #pragma unroll
    for (int b = 0; b < 4; b++) {
        UNPACK2(vr[0][b], vr[1][b], acc[0][b]);
        UNPACK2(vr[2][b], vr[3][b], acc[1][b]);
    }
    float* p = g_part + (size_t)s * R4H * B;
    #pragma unroll
    for (int r = 0; r < 4; r++)
        *(float4*)(p + (size_t)(myrow + r) * B + bcol) =
            make_float4(vr[r][0], vr[r][1], vr[r][2], vr[r][3]);
}

// ---------------- cell: combine 16 partials + bias + LSTM cell ----------------
__device__ void cell_phase(const float* __restrict__ bias,
                           float* __restrict__ cT, float* __restrict__ hOut)
{
    if (threadIdx.x >= 64) return;
    const int idx = blockIdx.x * 64 + threadIdx.x;        // 0..32767
    const int j = idx >> 5, b = idx & 31;
    float g[4];
    #pragma unroll
    for (int gg = 0; gg < 4; gg++) {
        float a = bias[gg * H + j];
        #pragma unroll
        for (int s2 = 0; s2 < NSLICE; s2++)
            a += g_part[((size_t)s2 * R4H + gg * H + j) * B + b];
        g[gg] = a;
    }
    float c_old = cT[j * B + b];
    float c_new = sigm(g[1]) * c_old + sigm(g[0]) * tanhf(g[2]);
    cT[j * B + b]   = c_new;
    hOut[j * B + b] = sigm(g[3]) * tanhf(c_new);
}

// ---------------- logits: 500 CTAs, CTA-local split-K2, fused argmax ----------------
__device__ void logits_phase(const float* __restrict__ h1T,
                             const float* __restrict__ outB,
                             float* __restrict__ out, int step)
{
    __shared__ float s_x[2][128 * B];                     // 32 KB
    __shared__ unsigned long long s_comb[4][32][8];       // 8 KB
    __shared__ float s_av[2][32];
    __shared__ int   s_ai[2][32];

    const int c = blockIdx.x;
    if (c >= LCTAS) return;
    const int tid = threadIdx.x;
    const int w = tid >> 5, lane = tid & 31;
    const int ks = w & 1, bh = (w >> 1) & 1, rgh = w >> 2;
    const int vrow = c * 64 + rgh * 32 + (lane >> 2) * 4;
    const int bcol = bh * 16 + (lane & 3) * 4;

    unsigned long long acc[2][4];
    #pragma unroll
    for (int a = 0; a < 2; a++)
        #pragma unroll
        for (int b = 0; b < 4; b++) acc[a][b] = 0ull;

    for (int ci = 0; ci < 4; ci++) {
        const float4* sA = (const float4*)(h1T + (size_t)(ci * 128) * B);
        const float4* sB = (const float4*)(h1T + (size_t)(512 + ci * 128) * B);
        float4* dA = (float4*)s_x[0];
        float4* dB = (float4*)s_x[1];
        #pragma unroll
        for (int i = 0; i < 4; i++) {
            dA[tid + i * 256] = sA[tid + i * 256];
            dB[tid + i * 256] = sB[tid + i * 256];
        }
        __syncthreads();

        const int kg0 = ks * 512 + ci * 128;
        const float* wp = g_outWT + (size_t)kg0 * V + vrow;
        const float* xp = s_x[ks] + bcol;
        #pragma unroll 4
        for (int kk = 0; kk < 128; kk++) {
            ulonglong2 w2 = *(const ulonglong2*)wp;
            float4 x4 = *(const float4*)xp;
            unsigned long long xx;
            PACKXX(xx, x4.x); FMA2(acc[0][0], w2.x, xx); FMA2(acc[1][0], w2.y, xx);
            PACKXX(xx, x4.y); FMA2(acc[0][1], w2.x, xx); FMA2(acc[1][1], w2.y, xx);
            PACKXX(xx, x4.z); FMA2(acc[0][2], w2.x, xx); FMA2(acc[1][2], w2.y, xx);
            PACKXX(xx, x4.w); FMA2(acc[0][3], w2.x, xx); FMA2(acc[1][3], w2.y, xx);
            wp += V; xp += B;
        }
        __syncthreads();
    }

    // CTA-local split-K combine
    if (ks) {
        #pragma unroll
        for (int a = 0; a < 8; a++) s_comb[w >> 1][lane][a] = acc[a >> 2][a & 3];
    }
    __syncthreads();
    if (!ks) {
        #pragma unroll
        for (int a = 0; a < 8; a++) {
            unsigned long long o = s_comb[w >> 1][lane][a];
            ADD2(acc[a >> 2][a & 3], acc[a >> 2][a & 3], o);
        }
        float4 b4 = *(const float4*)(outB + vrow);
        float vr[4][4];
        #pragma unroll
        for (int b = 0; b < 4; b++) {
            UNPACK2(vr[0][b], vr[1][b], acc[0][b]);
            UNPACK2(vr[2][b], vr[3][b], acc[1][b]);
            vr[0][b] += b4.x; vr[1][b] += b4.y; vr[2][b] += b4.z; vr[3][b] += b4.w;
        }
        float mval[4]; int midx[4];
        #pragma unroll
        for (int b = 0; b < 4; b++) {
            // store logits for batch (bcol+b), rows vrow..vrow+3
            *(float4*)(out + (size_t)(bcol + b) * (L * V) + (size_t)step * V + vrow) =
                make_float4(vr[0][b], vr[1][b], vr[2][b], vr[3][b]);
            float bv = vr[0][b]; int bi = vrow;
            #pragma unroll
            for (int r = 1; r < 4; r++)
                if (vr[r][b] > bv) { bv = vr[r][b]; bi = vrow + r; }
            mval[b] = bv; midx[b] = bi;
        }
        // reduce over 8 row-lanes (stride-4 lane groups)
        #pragma unroll
        for (int off = 16; off >= 4; off >>= 1) {
            #pragma unroll
            for (int b = 0; b < 4; b++) {
                float ov = __shfl_down_sync(0xffffffffu, mval[b], off);
                int   oi = __shfl_down_sync(0xffffffffu, midx[b], off);
                if (ov > mval[b] || (ov == mval[b] && oi < midx[b])) {
                    mval[b] = ov; midx[b] = oi;
                }
            }
        }
        if (lane < 4) {
            #pragma unroll
            for (int b = 0; b < 4; b++) {
                s_av[rgh][bh * 16 + lane * 4 + b] = mval[b];
                s_ai[rgh][bh * 16 + lane * 4 + b] = midx[b];
            }
        }
    }
    __syncthreads();
    if (tid < 32) {
        float v0 = s_av[0][tid], v1 = s_av[1][tid];
        int   i0 = s_ai[0][tid], i1 = s_ai[1][tid];
        bool take1 = (v1 > v0) || (v1 == v0 && i1 < i0);
        g_pval[c * B + tid] = take1 ? v1 : v0;
        g_pidx[c * B + tid] = take1 ? i1 : i0;
    }
}

// ---------------- argmax final + next-token embedding gather ----------------
__device__ void argmax_gather_phase(const float* __restrict__ emb, bool do_argmax)
{
    __shared__ float sval[256];
    __shared__ int   sidx[256];
    const int c = blockIdx.x;
    if (c >= B) return;
    const int b = c, tid = threadIdx.x;
    int tk;
    if (do_argmax) {
        float bv = -INFINITY; int bi = 0x7fffffff;
        for (int i2 = tid; i2 < LCTAS; i2 += 256) {
            float v = g_pval[i2 * B + b]; int i = g_pidx[i2 * B + b];
            if (v > bv || (v == bv && i < bi)) { bv = v; bi = i; }
        }
        sval[tid] = bv; sidx[tid] = bi;
        __syncthreads();
        for (int off = 128; off; off >>= 1) {
            if (tid < off) {
                float v = sval[tid + off]; int i = sidx[tid + off];
                if (v > sval[tid] || (v == sval[tid] && i < sidx[tid])) {
                    sval[tid] = v; sidx[tid] = i;
                }
            }
            __syncthreads();
        }
        tk = sidx[0];
    } else {
        tk = BOS;
    }
    for (int k = tid; k < E; k += 256)
        g_xdT[k * B + b] = emb[(size_t)tk * E + k];
}

// ---------------- persistent model kernel ----------------
__global__ __launch_bounds__(256, 4) void model_kernel(
    const float* __restrict__ emb,
    const float* __restrict__ eb0, const float* __restrict__ eb1,
    const float* __restrict__ db0, const float* __restrict__ db1,
    const float* __restrict__ outB,
    float* __restrict__ out)
{
    const int tid = threadIdx.x;
    for (int i = blockIdx.x * 256 + tid; i < H * B; i += NB * 256) {
        g_h0T[0][i] = 0.f; g_h1T[0][i] = 0.f;
        g_c0T[i] = 0.f;    g_c1T[i] = 0.f;
    }
    grid_barrier();

    int p0 = 0, p1 = 0;
    for (int t = 0; t < T; t++) {
        gates_phase(g_xsT + (size_t)t * E * B, E, g_h0T[p0], g_WTe0, E + H);
        grid_barrier();
        cell_phase(eb0, g_c0T, g_h0T[p0 ^ 1]);
        grid_barrier(); p0 ^= 1;
        gates_phase(g_h0T[p0], H, g_h1T[p1], g_WTe1, 2 * H);
        grid_barrier();
        cell_phase(eb1, g_c1T, g_h1T[p1 ^ 1]);
        grid_barrier(); p1 ^= 1;
    }

    argmax_gather_phase(emb, false);
    grid_barrier();

    for (int s = 0; s < L; s++) {
        gates_phase(g_xdT, E, g_h0T[p0], g_WTd0, E + H);
        grid_barrier();
        cell_phase(db0, g_c0T, g_h0T[p0 ^ 1]);
        grid_barrier(); p0 ^= 1;
        gates_phase(g_h0T[p0], H, g_h1T[p1], g_WTd1, 2 * H);
        grid_barrier();
        cell_phase(db1, g_c1T, g_h1T[p1 ^ 1]);
        grid_barrier(); p1 ^= 1;
        logits_phase(g_h1T[p1], outB, out, s);
        grid_barrier();
        argmax_gather_phase(emb, true);
        grid_barrier();
    }
}

// ---------------- host orchestration ----------------
extern "C" void kernel_launch(void* const* d_in, const int* in_sizes, int n_in,
                              void* d_out, int out_size)
{
    const int*   src   = (const int*)  d_in[0];
    const float* emb   = (const float*)d_in[1];
    const float* eWih0 = (const float*)d_in[2];
    const float* eWhh0 = (const float*)d_in[3];
    const float* eb0   = (const float*)d_in[4];
    const float* eWih1 = (const float*)d_in[5];
    const float* eWhh1 = (const float*)d_in[6];
    const float* eb1   = (const float*)d_in[7];
    const float* dWih0 = (const float*)d_in[8];
    const float* dWhh0 = (const float*)d_in[9];
    const float* db0   = (const float*)d_in[10];
    const float* dWih1 = (const float*)d_in[11];
    const float* dWhh1 = (const float*)d_in[12];
    const float* db1   = (const float*)d_in[13];
    const float* outW  = (const float*)d_in[14];
    const float* outB  = (const float*)d_in[15];
    float* out = (float*)d_out;

    float *xsT, *wte0, *wte1, *wtd0, *wtd1, *owt;
    cudaGetSymbolAddress((void**)&xsT,  g_xsT);
    cudaGetSymbolAddress((void**)&wte0, g_WTe0);
    cudaGetSymbolAddress((void**)&wte1, g_WTe1);
    cudaGetSymbolAddress((void**)&wtd0, g_WTd0);
    cudaGetSymbolAddress((void**)&wtd1, g_WTd1);
    cudaGetSymbolAddress((void**)&owt,  g_outWT);

    // weight transposes (graph nodes, run each replay)
    transpose_kernel<<<dim3(E / 32,  R4H / 32), 256>>>(eWih0, wte0, E, R4H, 0);
    transpose_kernel<<<dim3(H / 32,  R4H / 32), 256>>>(eWhh0, wte0, H, R4H, E);
    transpose_kernel<<<dim3(H / 32,  R4H / 32), 256>>>(eWih1, wte1, H, R4H, 0);
    transpose_kernel<<<dim3(H / 32,  R4H / 32), 256>>>(eWhh1, wte1, H, R4H, H);
    transpose_kernel<<<dim3(E / 32,  R4H / 32), 256>>>(dWih0, wtd0, E, R4H, 0);
    transpose_kernel<<<dim3(H / 32,  R4H / 32), 256>>>(dWhh0, wtd0, H, R4H, E);
    transpose_kernel<<<dim3(H / 32,  R4H / 32), 256>>>(dWih1, wtd1, H, R4H, 0);
    transpose_kernel<<<dim3(H / 32,  R4H / 32), 256>>>(dWhh1, wtd1, H, R4H, H);
    transpose_kernel<<<dim3(H / 32,  V   / 32), 256>>>(outW,  owt,  H, V,   0);

    gather_x_kernel<<<dim3(E / 128, T), 256>>>(emb, src, T, xsT);

    model_kernel<<<NB, 256>>>(emb, eb0, eb1, db0, db1, outB, out);
}